// round 7
// baseline (speedup 1.0000x reference)
#include <cuda_runtime.h>
#include <cstdint>

#define DDIM 128
#define MAXN 50048
#define MAXE 2097152
#define PADB 132   // Bs row stride (tf32 words)
#define PADA 36    // As row stride (floats)

// Scratch (allocation-free: __device__ globals)
__device__ float g_agg[(size_t)MAXN * DDIM];
__device__ float g_h  [(size_t)MAXN * DDIM];
__device__ float g_x  [(size_t)MAXN * DDIM];
__device__ int   g_cnt[MAXN];
__device__ int   g_rowptr[MAXN + 1];
__device__ int   g_cursor[MAXN];
__device__ int   g_esrc[MAXE];

// ---------------------------------------------------------------------------
// Helpers
// ---------------------------------------------------------------------------
__device__ __forceinline__ uint32_t f2tf32(float f) {
    uint32_t r;
    asm("cvt.rna.tf32.f32 %0, %1;" : "=r"(r) : "f"(f));
    return r;
}
__device__ __forceinline__ uint32_t smem_u32(const void* p) {
    uint32_t a;
    asm("{ .reg .u64 t; cvta.to.shared.u64 t, %1; cvt.u32.u64 %0, t; }"
        : "=r"(a) : "l"(p));
    return a;
}
__device__ __forceinline__ void cp_async16(uint32_t dst, const void* src, bool pred) {
    int sz = pred ? 16 : 0;
    asm volatile("cp.async.ca.shared.global [%0], [%1], 16, %2;"
                 :: "r"(dst), "l"(src), "r"(sz));
}
__device__ __forceinline__ void cp_commit() {
    asm volatile("cp.async.commit_group;" ::: "memory");
}

__device__ __forceinline__ void mma_m16n8k8(float c[4], const uint32_t a[4],
                                            const uint32_t b[2]) {
    asm volatile(
        "mma.sync.aligned.m16n8k8.row.col.f32.tf32.tf32.f32 "
        "{%0,%1,%2,%3}, {%4,%5,%6,%7}, {%8,%9}, {%0,%1,%2,%3};\n"
        : "+f"(c[0]), "+f"(c[1]), "+f"(c[2]), "+f"(c[3])
        : "r"(a[0]), "r"(a[1]), "r"(a[2]), "r"(a[3]), "r"(b[0]), "r"(b[1]));
}

// ---------------------------------------------------------------------------
// Edge dtype self-detection (int64 vs int32)
// ---------------------------------------------------------------------------
__device__ __forceinline__ bool edges_are_i64(const void* ei, int N) {
    const long long* e64 = (const long long*)ei;
#pragma unroll
    for (int i = 0; i < 4; i++) {
        long long v = e64[i];
        if (v < 0 || v >= (long long)N) return false;
    }
    return true;
}

__global__ void zero_cnt_kernel(int* cnt, int n) {
    int i = blockIdx.x * blockDim.x + threadIdx.x;
    if (i < n) cnt[i] = 0;
}

__global__ void hist_kernel(int* cnt, const void* ei, int E, int N) {
    int i = blockIdx.x * blockDim.x + threadIdx.x;
    if (i >= E) return;
    bool is64 = edges_are_i64(ei, N);
    int d;
    if (is64) d = (int)((const long long*)ei)[E + i];
    else      d = ((const int*)ei)[E + i];
    atomicAdd(&cnt[d], 1);
}

__global__ void scan_kernel(const int* __restrict__ cnt, int* __restrict__ rowptr,
                            int* __restrict__ cursor, int N) {
    __shared__ int part[1024];
    int tid = threadIdx.x;
    int chunk = (N + 1023) / 1024;
    int start = tid * chunk;
    int end = min(start + chunk, N);
    int s = 0;
    for (int i = start; i < end; i++) s += cnt[i];
    part[tid] = s;
    __syncthreads();
    for (int off = 1; off < 1024; off <<= 1) {
        int v = (tid >= off) ? part[tid - off] : 0;
        __syncthreads();
        part[tid] += v;
        __syncthreads();
    }
    int run = (tid == 0) ? 0 : part[tid - 1];
    for (int i = start; i < end; i++) {
        rowptr[i] = run;
        cursor[i] = run;
        run += cnt[i];
    }
    if (end == N) rowptr[N] = run;
}

__global__ void bucket_kernel(int* __restrict__ cursor, int* __restrict__ esrc,
                              const void* ei, int E, int N) {
    int i = blockIdx.x * blockDim.x + threadIdx.x;
    if (i >= E) return;
    bool is64 = edges_are_i64(ei, N);
    int s, d;
    if (is64) {
        s = (int)((const long long*)ei)[i];
        d = (int)((const long long*)ei)[E + i];
    } else {
        s = ((const int*)ei)[i];
        d = ((const int*)ei)[E + i];
    }
    int pos = atomicAdd(&cursor[d], 1);
    esrc[pos] = s;
}

// ---------------------------------------------------------------------------
// agg[i] = x[i] + sum_{s in in-neighbors(i)} x[s].  One warp per node.
// ---------------------------------------------------------------------------
__global__ void gather_agg_kernel(float* __restrict__ agg, const float* __restrict__ x,
                                  const int* __restrict__ rowptr,
                                  const int* __restrict__ esrc, int N) {
    int node = blockIdx.x * (blockDim.x >> 5) + (threadIdx.x >> 5);
    if (node >= N) return;
    int lane = threadIdx.x & 31;

    float4 acc = ((const float4*)(x + (size_t)node * DDIM))[lane];
    int b = rowptr[node];
    int e = rowptr[node + 1];

    for (int base = b; base < e; base += 32) {
        int m = min(32, e - base);
        int sv = (lane < m) ? esrc[base + lane] : 0;
#pragma unroll 4
        for (int j = 0; j < m; j++) {
            int s = __shfl_sync(0xffffffffu, sv, j);
            float4 v = ((const float4*)(x + (size_t)s * DDIM))[lane];
            acc.x += v.x; acc.y += v.y; acc.z += v.z; acc.w += v.w;
        }
    }
    ((float4*)(agg + (size_t)node * DDIM))[lane] = acc;
}

// ---------------------------------------------------------------------------
// Persistent pipelined tf32 mma.sync GEMM, 2 CTAs/SM:
//   C[M,128] = relu(A[M,128] @ W[128,128] + bias)
// W staged once per block (tf32, k-major). A staged fp32 via cp.async with a
// 2-buffer ring pipelined ACROSS chunk/tile boundaries (one group in flight).
// 8 warps, 4(m)x2(n), 32x64 each via 2x8 m16n8k8 tiles.
// ---------------------------------------------------------------------------
#define SM_BIAS  0
#define SM_B     128                             // floats offset
#define SM_A     (128 + 128 * PADB)              // floats offset
#define GEMM_SMEM ((128 + 128 * PADB + 2 * 128 * PADA) * 4)   // ~102.5 KB

__device__ __forceinline__ void prefetch_chunk(const float* __restrict__ A, int M,
                                               int row0, int c, float* __restrict__ dst,
                                               int tid) {
#pragma unroll
    for (int j = 0; j < 4; j++) {
        int i = tid + j * 256;                   // 0..1023
        int r = i >> 3;
        int cc = (i & 7) << 2;
        uint32_t d = smem_u32(dst + r * PADA + cc);
        const float* src = A + (size_t)(row0 + r) * DDIM + c * 32 + cc;
        cp_async16(d, src, row0 + r < M);
    }
    cp_commit();
}

__device__ __forceinline__ void compute_chunk(
    const float* __restrict__ As_c, const uint32_t* __restrict__ Bs, int kbase,
    int mrow, int ncol, int g, int t, float acc[2][8][4]) {
#pragma unroll
    for (int ks = 0; ks < 4; ks++) {
        int kk = ks * 8;
        uint32_t a[2][4];
#pragma unroll
        for (int mt = 0; mt < 2; mt++) {
            const float* b0 = As_c + (mrow + mt * 16 + g) * PADA + kk + t;
            const float* b1 = As_c + (mrow + mt * 16 + g + 8) * PADA + kk + t;
            a[mt][0] = f2tf32(b0[0]);
            a[mt][1] = f2tf32(b1[0]);
            a[mt][2] = f2tf32(b0[4]);
            a[mt][3] = f2tf32(b1[4]);
        }
        uint32_t b[8][2];
#pragma unroll
        for (int nt = 0; nt < 8; nt++) {
            int cc = ncol + nt * 8 + g;
            b[nt][0] = Bs[(kbase + kk + t) * PADB + cc];
            b[nt][1] = Bs[(kbase + kk + t + 4) * PADB + cc];
        }
#pragma unroll
        for (int mt = 0; mt < 2; mt++)
#pragma unroll
            for (int nt = 0; nt < 8; nt++)
                mma_m16n8k8(acc[mt][nt], a[mt], b[nt]);
    }
}

__global__ void __launch_bounds__(256, 2)
gemm_tf32_pipe(const float* __restrict__ A, const float* __restrict__ W,
               const float* __restrict__ bias, float* __restrict__ C,
               int M, int ntiles) {
    extern __shared__ float sm[];
    float* bias_s = sm + SM_BIAS;
    uint32_t* Bs = (uint32_t*)(sm + SM_B);
    float* As = sm + SM_A;                       // [2][128][PADA]

    int tid = threadIdx.x;
    int wid = tid >> 5, lane = tid & 31;
    int g = lane >> 2, t = lane & 3;
    int mrow = (wid >> 1) * 32, ncol = (wid & 1) * 64;

    if (tid < 128) bias_s[tid] = bias[tid];
    // Stage W once (k-major, tf32)
    for (int i = tid; i < 4096; i += 256) {
        int k = i >> 5;
        int n4 = (i & 31) << 2;
        float4 v = *(const float4*)(W + (size_t)k * DDIM + n4);
        uint32_t* p = &Bs[k * PADB + n4];
        p[0] = f2tf32(v.x); p[1] = f2tf32(v.y);
        p[2] = f2tf32(v.z); p[3] = f2tf32(v.w);
    }
    __syncthreads();

    // Continuous chunk pipeline across tiles; one cp.async group in flight.
    int buf = 0;
    if (blockIdx.x < ntiles)
        prefetch_chunk(A, M, blockIdx.x << 7, 0, As, tid);

    for (int tt = blockIdx.x; tt < ntiles; tt += gridDim.x) {
        int row0 = tt << 7;
        float acc[2][8][4];
#pragma unroll
        for (int mt = 0; mt < 2; mt++)
#pragma unroll
            for (int nt = 0; nt < 8; nt++)
#pragma unroll
                for (int j = 0; j < 4; j++) acc[mt][nt][j] = 0.f;

#pragma unroll
        for (int c = 0; c < 4; c++) {
            asm volatile("cp.async.wait_group 0;" ::: "memory");
            __syncthreads();
            // issue next chunk (next tile's chunk 0 when c==3)
            int nc = (c + 1) & 3;
            int ntile = (c == 3) ? tt + (int)gridDim.x : tt;
            if (ntile < ntiles)
                prefetch_chunk(A, M, ntile << 7, nc, As + (buf ^ 1) * 128 * PADA, tid);
            compute_chunk(As + buf * 128 * PADA, Bs, c * 32, mrow, ncol, g, t, acc);
            buf ^= 1;
        }

        // Epilogue: bias + relu (overlaps next tile's chunk-0 load)
#pragma unroll
        for (int nt = 0; nt < 8; nt++) {
            int col = ncol + nt * 8 + t * 2;
            float2 bb = *(const float2*)(bias_s + col);
#pragma unroll
            for (int mt = 0; mt < 2; mt++) {
                int r0 = row0 + mrow + mt * 16 + g;
                int r1 = r0 + 8;
                if (r0 < M) {
                    float2 o;
                    o.x = fmaxf(acc[mt][nt][0] + bb.x, 0.f);
                    o.y = fmaxf(acc[mt][nt][1] + bb.y, 0.f);
                    *(float2*)(C + (size_t)r0 * DDIM + col) = o;
                }
                if (r1 < M) {
                    float2 o;
                    o.x = fmaxf(acc[mt][nt][2] + bb.x, 0.f);
                    o.y = fmaxf(acc[mt][nt][3] + bb.y, 0.f);
                    *(float2*)(C + (size_t)r1 * DDIM + col) = o;
                }
            }
        }
    }
}

// ---------------------------------------------------------------------------
extern "C" void kernel_launch(void* const* d_in, const int* in_sizes, int n_in,
                              void* d_out, int out_size) {
    const float* x  = (const float*)d_in[0];
    const void*  ei = d_in[1];
    const float* W1 = (const float*)d_in[2];
    const float* b1 = (const float*)d_in[3];
    const float* W2 = (const float*)d_in[4];
    const float* b2 = (const float*)d_in[5];

    int N = in_sizes[0] / DDIM;
    int E = in_sizes[1] / 2;
    int L = in_sizes[3] / DDIM;

    float* out = (float*)d_out;

    float *agg, *h, *xb;
    int *cnt, *rowptr, *cursor, *esrc;
    cudaGetSymbolAddress((void**)&agg,    g_agg);
    cudaGetSymbolAddress((void**)&h,      g_h);
    cudaGetSymbolAddress((void**)&xb,     g_x);
    cudaGetSymbolAddress((void**)&cnt,    g_cnt);
    cudaGetSymbolAddress((void**)&rowptr, g_rowptr);
    cudaGetSymbolAddress((void**)&cursor, g_cursor);
    cudaGetSymbolAddress((void**)&esrc,   g_esrc);

    static int smem_set = 0;
    if (!smem_set) {
        cudaFuncSetAttribute(gemm_tf32_pipe,
                             cudaFuncAttributeMaxDynamicSharedMemorySize, GEMM_SMEM);
        smem_set = 1;
    }

    // ---- CSR build (once per launch) ----
    zero_cnt_kernel<<<(N + 255) / 256, 256>>>(cnt, N);
    hist_kernel<<<(E + 255) / 256, 256>>>(cnt, ei, E, N);
    scan_kernel<<<1, 1024>>>(cnt, rowptr, cursor, N);
    bucket_kernel<<<(E + 255) / 256, 256>>>(cursor, esrc, ei, E, N);

    const float* cur = x;
    int gather_blocks = (N + 7) / 8;
    int ntiles = (N + 127) / 128;
    int gemm_grid = 2 * 148;
    if (gemm_grid > ntiles) gemm_grid = ntiles;

    for (int l = 0; l < L; l++) {
        gather_agg_kernel<<<gather_blocks, 256>>>(agg, cur, rowptr, esrc, N);
        gemm_tf32_pipe<<<gemm_grid, 256, GEMM_SMEM>>>(
            agg, W1 + (size_t)l * DDIM * DDIM, b1 + (size_t)l * DDIM, h, N, ntiles);
        float* dst = (l == L - 1) ? out : xb;
        gemm_tf32_pipe<<<gemm_grid, 256, GEMM_SMEM>>>(
            h, W2 + (size_t)l * DDIM * DDIM, b2 + (size_t)l * DDIM, dst, N, ntiles);
        cur = dst;
    }
}